// round 2
// baseline (speedup 1.0000x reference)
#include <cuda_runtime.h>

#define U_N 100000
#define I_N 50000
#define D_N 64
#define A_N 20000
#define B_N 30000
#define E_N 2000000
#define NN  (U_N + I_N)   // 150000

// Scratch (allocation-free rule: __device__ globals)
__device__ __align__(256) float g_a[NN * D_N];     // 38.4 MB
__device__ __align__(256) float g_b[NN * D_N];     // 38.4 MB
__device__ __align__(256) float g_deg[NN];
__device__ __align__(256) float g_dinv[NN];
__device__ __align__(256) float g_coef[E_N];       // 8 MB

__device__ __forceinline__ float warp_sum(float s) {
#pragma unroll
    for (int o = 16; o; o >>= 1) s += __shfl_xor_sync(0xffffffffu, s, o);
    return s;
}

__device__ __forceinline__ void red_add_v4(float* addr, float4 v) {
    asm volatile("red.global.add.v4.f32 [%0], {%1,%2,%3,%4};"
                 :: "l"(addr), "f"(v.x), "f"(v.y), "f"(v.z), "f"(v.w)
                 : "memory");
}

// ---------------- Prologue ----------------

// L2-normalize user rows -> x and acc. One warp per row, lane handles float2.
__global__ void user_kernel(const float* __restrict__ uw,
                            float* __restrict__ x, float* __restrict__ acc) {
    int w    = (blockIdx.x * blockDim.x + threadIdx.x) >> 5;
    int lane = threadIdx.x & 31;
    if (w >= U_N) return;
    float2 v = ((const float2*)uw)[w * 32 + lane];
    float s  = warp_sum(v.x * v.x + v.y * v.y);
    float r  = 1.0f / fmaxf(sqrtf(s), 1e-12f);
    float2 o = make_float2(v.x * r, v.y * r);
    ((float2*)x)[w * 32 + lane]   = o;
    ((float2*)acc)[w * 32 + lane] = o;
}

// Item embedding: feat = [audio(64), artist+album(64)]; out = l2norm(feat @ W^T + b)
// One warp per item; thread t computes dims t and t+32. W transposed in shared.
__global__ void item_kernel(const float* __restrict__ audio,
                            const float* __restrict__ art,
                            const float* __restrict__ alb,
                            const float* __restrict__ W,     // [64, 128]
                            const float* __restrict__ bias,  // [64]
                            const int* __restrict__ aid,
                            const int* __restrict__ bid,
                            float* __restrict__ x, float* __restrict__ acc) {
    __shared__ float WT[128 * 64];   // WT[k*64+d] = W[d*128+k]
    __shared__ float feat[8][128];
    int tid = threadIdx.x;
    for (int idx = tid; idx < 64 * 128; idx += 256) {
        int d = idx >> 7, k = idx & 127;
        WT[k * 64 + d] = W[idx];
    }
    __syncthreads();

    int w = tid >> 5, lane = tid & 31;
    int item = blockIdx.x * 8 + w;
    if (item < I_N) {
        int a = aid[item], bb = bid[item];
        feat[w][lane]      = audio[item * 64 + lane];
        feat[w][lane + 32] = audio[item * 64 + lane + 32];
        feat[w][64 + lane] = art[a * 64 + lane]      + alb[bb * 64 + lane];
        feat[w][96 + lane] = art[a * 64 + lane + 32] + alb[bb * 64 + lane + 32];
    }
    __syncwarp();
    if (item >= I_N) return;

    float a0 = 0.f, a1 = 0.f;
#pragma unroll
    for (int k = 0; k < 128; k++) {
        float f = feat[w][k];
        a0 = fmaf(f, WT[k * 64 + lane],      a0);
        a1 = fmaf(f, WT[k * 64 + lane + 32], a1);
    }
    a0 += bias[lane];
    a1 += bias[lane + 32];
    float s = warp_sum(a0 * a0 + a1 * a1);
    float r = 1.0f / fmaxf(sqrtf(s), 1e-12f);
    int base = (U_N + item) * 64;
    x[base + lane]        = a0 * r;
    x[base + lane + 32]   = a1 * r;
    acc[base + lane]      = a0 * r;
    acc[base + lane + 32] = a1 * r;
}

__global__ void deg_init_kernel() {
    int n = blockIdx.x * blockDim.x + threadIdx.x;
    if (n < NN) g_deg[n] = 1.0f;   // self loop weight
}

__global__ void deg_edge_kernel(const float* __restrict__ ew,
                                const int* __restrict__ ui,
                                const int* __restrict__ ii) {
    int e = blockIdx.x * blockDim.x + threadIdx.x;
    if (e >= E_N) return;
    float w = fmaxf(ew[e], 1e-6f);
    atomicAdd(&g_deg[ui[e]], w);
    atomicAdd(&g_deg[U_N + ii[e]], w);
}

__global__ void dinv_kernel() {
    int n = blockIdx.x * blockDim.x + threadIdx.x;
    if (n < NN) g_dinv[n] = rsqrtf(g_deg[n]);
}

__global__ void coef_kernel(const float* __restrict__ ew,
                            const int* __restrict__ ui,
                            const int* __restrict__ ii) {
    int e = blockIdx.x * blockDim.x + threadIdx.x;
    if (e >= E_N) return;
    g_coef[e] = g_dinv[ui[e]] * fmaxf(ew[e], 1e-6f) * g_dinv[U_N + ii[e]];
}

// ---------------- Propagation ----------------

// xn = dinv^2 * x   (self loop init)
__global__ void self_init_kernel(const float* __restrict__ x, float* __restrict__ xn) {
    int idx = blockIdx.x * blockDim.x + threadIdx.x;   // over NN*16 float4s
    if (idx >= NN * 16) return;
    int n = idx >> 4;
    float di = g_dinv[n];
    float c = di * di;
    float4 v = ((const float4*)x)[idx];
    ((float4*)xn)[idx] = make_float4(c * v.x, c * v.y, c * v.z, c * v.w);
}

// acc += xin; xninit = dinv^2 * xin
__global__ void fuse_kernel(float* __restrict__ acc, const float* __restrict__ xin,
                            float* __restrict__ xninit) {
    int idx = blockIdx.x * blockDim.x + threadIdx.x;
    if (idx >= NN * 16) return;
    int n = idx >> 4;
    float di = g_dinv[n];
    float c = di * di;
    float4 v = ((const float4*)xin)[idx];
    float4 a = ((float4*)acc)[idx];
    ((float4*)acc)[idx]    = make_float4(a.x + v.x, a.y + v.y, a.z + v.z, a.w + v.w);
    ((float4*)xninit)[idx] = make_float4(c * v.x, c * v.y, c * v.z, c * v.w);
}

// Edge scatter: 16 threads per edge, each handles one float4 of D=64.
// Both directions fused: dst[i+U] += c*x[u],  dst[u] += c*x[i+U].
__global__ void edge_kernel(const float* __restrict__ x, float* __restrict__ xn,
                            const float* __restrict__ coef,
                            const int* __restrict__ ui, const int* __restrict__ ii) {
    int t = blockIdx.x * blockDim.x + threadIdx.x;
    int e = t >> 4;
    if (e >= E_N) return;
    int q = (t & 15) << 2;
    float c = __ldg(coef + e);
    int u  = __ldg(ui + e);
    int it = U_N + __ldg(ii + e);
    float4 a = *(const float4*)(x + u * 64 + q);
    float4 b = *(const float4*)(x + it * 64 + q);
    red_add_v4(xn + it * 64 + q, make_float4(c * a.x, c * a.y, c * a.z, c * a.w));
    red_add_v4(xn + u * 64 + q,  make_float4(c * b.x, c * b.y, c * b.z, c * b.w));
}

// out = l2norm((acc + xlast) / 4); in-place on acc (= d_out). One warp per row.
__global__ void final_kernel(float* __restrict__ acc, const float* __restrict__ xlast) {
    int w    = (blockIdx.x * blockDim.x + threadIdx.x) >> 5;
    int lane = threadIdx.x & 31;
    if (w >= NN) return;
    float2 va = ((const float2*)acc)[w * 32 + lane];
    float2 vb = ((const float2*)xlast)[w * 32 + lane];
    float x0 = (va.x + vb.x) * 0.25f;
    float x1 = (va.y + vb.y) * 0.25f;
    float s  = warp_sum(x0 * x0 + x1 * x1);
    float r  = 1.0f / fmaxf(sqrtf(s), 1e-12f);
    ((float2*)acc)[w * 32 + lane] = make_float2(x0 * r, x1 * r);
}

// ---------------- Launch ----------------

extern "C" void kernel_launch(void* const* d_in, const int* in_sizes, int n_in,
                              void* d_out, int out_size) {
    const float* user_w      = (const float*)d_in[0];
    const float* item_audio  = (const float*)d_in[1];
    const float* artist_w    = (const float*)d_in[2];
    const float* album_w     = (const float*)d_in[3];
    const float* proj_W      = (const float*)d_in[4];
    const float* proj_b      = (const float*)d_in[5];
    const float* edge_weight = (const float*)d_in[6];
    const int*   u_idx       = (const int*)d_in[7];
    const int*   i_idx       = (const int*)d_in[8];
    const int*   artist_ids  = (const int*)d_in[9];
    const int*   album_ids   = (const int*)d_in[10];
    float* acc = (float*)d_out;

    float *pa, *pb, *pcoef;
    cudaGetSymbolAddress((void**)&pa, g_a);
    cudaGetSymbolAddress((void**)&pb, g_b);
    cudaGetSymbolAddress((void**)&pcoef, g_coef);

    const int T = 256;
    // Prologue
    user_kernel<<<(U_N * 32) / T, T>>>(user_w, pa, acc);
    item_kernel<<<I_N / 8, T>>>(item_audio, artist_w, album_w, proj_W, proj_b,
                                artist_ids, album_ids, pa, acc);
    deg_init_kernel<<<(NN + T - 1) / T, T>>>();
    deg_edge_kernel<<<(E_N + T - 1) / T, T>>>(edge_weight, u_idx, i_idx);
    dinv_kernel<<<(NN + T - 1) / T, T>>>();
    coef_kernel<<<(E_N + T - 1) / T, T>>>(edge_weight, u_idx, i_idx);

    const int elem_blocks = (NN * 16 + T - 1) / T;
    const int edge_blocks = (E_N * 16) / T;

    // Layer 1: x0 in a
    self_init_kernel<<<elem_blocks, T>>>(pa, pb);
    edge_kernel<<<edge_blocks, T>>>(pa, pb, pcoef, u_idx, i_idx);   // b = x1
    // Layer 2
    fuse_kernel<<<elem_blocks, T>>>(acc, pb, pa);                   // acc+=x1; a=dinv2*x1
    edge_kernel<<<edge_blocks, T>>>(pb, pa, pcoef, u_idx, i_idx);   // a = x2
    // Layer 3
    fuse_kernel<<<elem_blocks, T>>>(acc, pa, pb);                   // acc+=x2; b=dinv2*x2
    edge_kernel<<<edge_blocks, T>>>(pa, pb, pcoef, u_idx, i_idx);   // b = x3
    // Epilogue
    final_kernel<<<(NN * 32 + T - 1) / T, T>>>(acc, pb);
}